// round 3
// baseline (speedup 1.0000x reference)
#include <cuda_runtime.h>
#include <math.h>

#define B_    16
#define CI    64
#define CO    64
#define NN    16384
#define MODES 2048
#define TEMBD 512
#define HN    8192   // NN/2, complex FFT length

// ---------------- scratch (device globals; no allocation allowed) ----------
__device__ float2 g_TW[HN];                 // exp(-2*pi*i*j/16384), j in [0,8192)
__device__ float  g_t[B_ * CI];             // temb projection
__device__ float2 g_xm[B_ * CI * MODES];    // 16 MB  x_ft[:, :, :modes] + t
__device__ float2 g_om[B_ * CO * MODES];    // 16 MB  einsum output

__device__ __forceinline__ float2 cmul(float2 a, float2 b) {
    return make_float2(a.x * b.x - a.y * b.y, a.x * b.y + a.y * b.x);
}
__device__ __forceinline__ float2 cadd(float2 a, float2 b) {
    return make_float2(a.x + b.x, a.y + b.y);
}
__device__ __forceinline__ float2 csub(float2 a, float2 b) {
    return make_float2(a.x - b.x, a.y - b.y);
}

__host__ __device__ constexpr int brev5c(int i) {
    return ((i & 1) << 4) | ((i & 2) << 2) | (i & 4) | ((i & 8) >> 2) | ((i & 16) >> 4);
}
__host__ __device__ constexpr int brev3c(int i) {
    return ((i & 1) << 2) | (i & 2) | ((i & 4) >> 2);
}

// padded smem index: +1 float2 per 256 (kills stride-256 bank conflicts)
#define PADI(i) ((i) + ((i) >> 8))
#define SBUF_ELEMS (HN + 32)          // 8224 float2 = 65792 B

// ---------------- twiddle table ---------------------------------------------
__global__ void k_tw() {
    int j = blockIdx.x * blockDim.x + threadIdx.x;
    if (j < HN) {
        float s, c;
        sincospif(-(float)j / (float)HN, &s, &c);   // -2*pi*j/16384
        g_TW[j] = make_float2(c, s);
    }
}

// ---------------- temb projection -------------------------------------------
__global__ void k_temb(const float* __restrict__ temb,
                       const float* __restrict__ dw,
                       const float* __restrict__ db) {
    __shared__ float red[256];
    int b   = blockIdx.x;
    int tid = threadIdx.x;
    int c   = tid & 63;
    int sl  = tid >> 6;
    const float* te = temb + b * TEMBD;
    const float* w  = dw + c * TEMBD;
    float p = 0.f;
    int k0 = sl * 128;
    #pragma unroll 4
    for (int k = k0; k < k0 + 128; k++) {
        float v = te[k];
        p += (v / (1.0f + expf(-v))) * w[k];
    }
    red[tid] = p;
    __syncthreads();
    if (sl == 0)
        g_t[b * CI + c] = red[c] + red[c + 64] + red[c + 128] + red[c + 192] + db[c];
}

// ---------------- register DIF FFT (natural in, bit-reversed out) -----------
template <int SIZE, int LOG>
__device__ __forceinline__ void fft_dif(float2* r, const float2* stw) {
    #pragma unroll
    for (int st = 0; st < LOG; st++) {
        const int span = SIZE >> (1 + st);
        #pragma unroll
        for (int g = 0; g < SIZE; g += 2 * span) {
            #pragma unroll
            for (int j = 0; j < span; j++) {
                float2 a = r[g + j];
                float2 b = r[g + j + span];
                r[g + j] = cadd(a, b);
                r[g + j + span] = cmul(csub(a, b), stw[j * (16 / span)]);
            }
        }
    }
}

// ---------------- four-step FFT-8192: 32(reg) x [32(reg) x 8(reg)] ----------
// Input : r[n1] = x[n1*256 + tid]  (caller preloads)
// Output: s[PADI(k)] = X[k] (forward) / sum e^{+2pi i} (inverse, unnormalized)
template <bool INV>
__device__ __forceinline__ void fft8192_4step(float2* s, const float2* stw,
                                              int tid, float2* r) {
    __syncthreads();   // protects s from previous use; stw ready

    // level 1: FFT-32 over n1 (stride 256), twiddle W_8192^{tid*k1}
    fft_dif<32, 5>(r, stw);
    {
        float2 w1 = g_TW[2 * tid];               // W_8192^tid
        if (INV) w1.y = -w1.y;
        float2 w12 = cmul(w1, w1);
        float2 w14 = cmul(w12, w12);
        float2 wc[4];
        wc[0] = make_float2(1.f, 0.f);
        wc[1] = w1;
        wc[2] = w12;
        wc[3] = cmul(w12, w1);
        #pragma unroll
        for (int g4 = 0; g4 < 8; g4++) {
            #pragma unroll
            for (int c = 0; c < 4; c++) {
                int k1 = g4 * 4 + c;
                s[k1 * 257 + tid] = cmul(r[brev5c(k1)], wc[c]);
            }
            if (g4 < 7) {
                #pragma unroll
                for (int c = 0; c < 4; c++) wc[c] = cmul(wc[c], w14);
            }
        }
    }
    __syncthreads();

    // level 2a: FFT-32 over n1' (stride 8 within each row), twiddle W_256^{n2'*k1'}
    const int k1 = tid & 31;
    const int n2p = tid >> 5;
    #pragma unroll
    for (int n1 = 0; n1 < 32; n1++)
        r[n1] = s[k1 * 257 + n1 * 8 + n2p];
    __syncthreads();
    fft_dif<32, 5>(r, stw);
    {
        float2 w2 = g_TW[64 * n2p];              // W_256^{n2'}
        if (INV) w2.y = -w2.y;
        float2 w22 = cmul(w2, w2);
        float2 w24 = cmul(w22, w22);
        float2 wc[4];
        wc[0] = make_float2(1.f, 0.f);
        wc[1] = w2;
        wc[2] = w22;
        wc[3] = cmul(w22, w2);
        #pragma unroll
        for (int g4 = 0; g4 < 8; g4++) {
            #pragma unroll
            for (int c = 0; c < 4; c++) {
                int k1p = g4 * 4 + c;
                s[k1 * 257 + k1p * 8 + n2p] = cmul(r[brev5c(k1p)], wc[c]);
            }
            if (g4 < 7) {
                #pragma unroll
                for (int c = 0; c < 4; c++) wc[c] = cmul(wc[c], w24);
            }
        }
    }
    __syncthreads();

    // level 2b: FFT-8 over n2' ; final index k = k1 + 32*k1' + 1024*k2'
    #pragma unroll
    for (int rr = 0; rr < 4; rr++) {
        const int k1b = (tid >> 5) + 8 * rr;
        #pragma unroll
        for (int j = 0; j < 8; j++)
            r[rr * 8 + j] = s[(tid & 31) * 257 + k1b * 8 + j];
    }
    __syncthreads();
    #pragma unroll
    for (int rr = 0; rr < 4; rr++)
        fft_dif<8, 3>(r + rr * 8, stw);
    #pragma unroll
    for (int rr = 0; rr < 4; rr++) {
        const int base = (tid & 31) + 32 * ((tid >> 5) + 8 * rr);
        #pragma unroll
        for (int j = 0; j < 8; j++) {
            const int k = base + 1024 * brev3c(j);
            s[PADI(k)] = r[rr * 8 + j];
        }
    }
    __syncthreads();
}

// ---------------- forward: rfft (first 2048 bins) + temb bias ---------------
__global__ void __launch_bounds__(256, 2) k_fwd(const float* __restrict__ x) {
    extern __shared__ unsigned char smem_u8[];
    float2* s = (float2*)smem_u8;
    __shared__ float2 stw[16];
    int row = blockIdx.x;
    int tid = threadIdx.x;

    if (tid < 16) stw[tid] = g_TW[tid * 512];   // W_32^j

    const float2* xr = (const float2*)(x + (size_t)row * NN);
    float2 r[32];
    #pragma unroll
    for (int n1 = 0; n1 < 32; n1++) r[n1] = xr[n1 * 256 + tid];

    fft8192_4step<false>(s, stw, tid, r);

    float tb = g_t[row];
    float2* outp = g_xm + (size_t)row * MODES;
    #pragma unroll
    for (int k = tid; k < MODES; k += 256) {
        float2 Zk = s[PADI(k)];
        float2 Zm = s[PADI((HN - k) & (HN - 1))];
        float2 E = make_float2(0.5f * (Zk.x + Zm.x), 0.5f * (Zk.y - Zm.y));
        float2 O = make_float2(0.5f * (Zk.y + Zm.y), 0.5f * (Zm.x - Zk.x));
        float2 WO = cmul(g_TW[k], O);
        outp[k] = make_float2(E.x + WO.x + tb, E.y + WO.y);
    }
}

// ---------------- einsum: out[b,o,m] = sum_i xm[b,i,m] * (wr+iwi)[i,o,m] ----
// 512 CTAs x 4 modes, 256 threads, tile 4b x 4o x 1m, double-buffered w chunks
#define WBUF 4160   // floats per buffer (wsr 2080 + wsi 2080)

__device__ __forceinline__ void eins_stage(const float* __restrict__ wr,
                                           const float* __restrict__ wi,
                                           float* dst, int ibc, int m0, int tid) {
    #pragma unroll
    for (int k = 0; k < 2; k++) {
        int l  = tid + 256 * k;          // 0..511
        int ii = l >> 6;                 // 0..7
        int o  = l & 63;
        size_t g = ((size_t)(ibc * 8 + ii) * CO + o) * MODES + m0;
        float4 vr = *(const float4*)(wr + g);
        float4 vi = *(const float4*)(wi + g);
        int sb = (ii * 4) * 65 + o;
        dst[sb]            = vr.x;
        dst[sb + 65]       = vr.y;
        dst[sb + 130]      = vr.z;
        dst[sb + 195]      = vr.w;
        dst[sb + 2080]       = vi.x;
        dst[sb + 2080 + 65]  = vi.y;
        dst[sb + 2080 + 130] = vi.z;
        dst[sb + 2080 + 195] = vi.w;
    }
}

__global__ void __launch_bounds__(256, 3) k_eins(const float* __restrict__ wr,
                                                 const float* __restrict__ wi) {
    extern __shared__ unsigned char smem_u8[];
    float*  smf = (float*)smem_u8;
    float2* xs  = (float2*)smf;            // [i][b][mm] : 64*16*4 float2 = 32KB
    float*  wbase = smf + 8192;            // 2 buffers x 4160 floats = 33.3KB

    int tid = threadIdx.x;
    int m0  = blockIdx.x * 4;
    int mg  = tid & 3;
    int og  = (tid >> 2) & 15;
    int bg  = tid >> 6;
    int b0  = bg * 4, o0 = og * 4;

    // stage all x modes for this chunk: 4096 float2, 16/thread
    for (int l = tid; l < 4096; l += 256) {
        int i  = l >> 6;
        int b  = (l >> 2) & 15;
        int mm = l & 3;
        xs[l] = g_xm[((size_t)(b * CI + i)) * MODES + m0 + mm];
    }
    eins_stage(wr, wi, wbase, 0, m0, tid);

    float2 acc[4][4];
    #pragma unroll
    for (int a = 0; a < 4; a++)
        #pragma unroll
        for (int o = 0; o < 4; o++) acc[a][o] = make_float2(0.f, 0.f);

    __syncthreads();   // xs + chunk 0 ready

    for (int ib = 0; ib < 8; ib++) {
        const float* wsr = wbase + (ib & 1) * WBUF;
        const float* wsi = wsr + 2080;

        // stage next chunk into the other buffer (overlaps compute below)
        if (ib < 7)
            eins_stage(wr, wi, wbase + ((ib + 1) & 1) * WBUF, ib + 1, m0, tid);

        #pragma unroll
        for (int ii = 0; ii < 8; ii++) {
            int i = ib * 8 + ii;
            float2 xv[4];
            #pragma unroll
            for (int bb = 0; bb < 4; bb++)
                xv[bb] = xs[i * 64 + (b0 + bb) * 4 + mg];
            #pragma unroll
            for (int oo = 0; oo < 4; oo++) {
                int sidx = (ii * 4 + mg) * 65 + o0 + oo;
                float wrv = wsr[sidx];
                float wiv = wsi[sidx];
                #pragma unroll
                for (int bb = 0; bb < 4; bb++) {
                    acc[bb][oo].x += xv[bb].x * wrv - xv[bb].y * wiv;
                    acc[bb][oo].y += xv[bb].x * wiv + xv[bb].y * wrv;
                }
            }
        }
        __syncthreads();   // readers done with buf[ib], buf[ib+1] fully stored
    }

    #pragma unroll
    for (int bb = 0; bb < 4; bb++)
        #pragma unroll
        for (int oo = 0; oo < 4; oo++)
            g_om[((size_t)(b0 + bb) * CO + (o0 + oo)) * MODES + m0 + mg] = acc[bb][oo];
}

// ---------------- inverse: zero-padded irfft(n=16384) of 2048 modes ---------
__global__ void __launch_bounds__(256, 2) k_inv(float* __restrict__ out) {
    extern __shared__ unsigned char smem_u8[];
    float2* s = (float2*)smem_u8;
    __shared__ float2 stw[16];
    int row = blockIdx.x;
    int tid = threadIdx.x;

    if (tid < 16) {
        float2 w = g_TW[tid * 512];
        stw[tid] = make_float2(w.x, -w.y);   // conj for inverse
    }

    const float2* Y = g_om + (size_t)row * MODES;
    // Build even/odd-packed spectrum C[k] = A[k] + i*B[k]
    for (int k = tid; k < HN; k += 256) {
        float2 Yl = make_float2(0.f, 0.f);
        float2 Yh = make_float2(0.f, 0.f);
        if (k < MODES) {
            Yl = Y[k];
            if (k == 0) Yl.y = 0.f;          // c2r ignores imag(DC)
        }
        if (k > HN - MODES) {                // k in [6145, 8191]
            float2 ym = Y[HN - k];
            Yh = make_float2(ym.x, -ym.y);
        }
        float2 A  = make_float2(Yl.x + Yh.x, Yl.y + Yh.y);
        float2 Bc = make_float2(Yl.x - Yh.x, Yl.y - Yh.y);
        float2 w  = g_TW[k];
        w.y = -w.y;                          // e^{+2pi i k/16384}
        float2 Bv = cmul(Bc, w);
        s[PADI(k)] = make_float2(A.x - Bv.y, A.y + Bv.x);
    }
    __syncthreads();

    float2 r[32];
    #pragma unroll
    for (int n1 = 0; n1 < 32; n1++)
        r[n1] = s[n1 * 257 + tid];           // PADI(n1*256+tid)

    fft8192_4step<true>(s, stw, tid, r);

    const float inv = 1.0f / (float)NN;
    float2* outp = (float2*)(out + (size_t)row * NN);
    #pragma unroll
    for (int m = tid; m < HN; m += 256) {
        float2 g = s[PADI(m)];
        outp[m] = make_float2(g.x * inv, g.y * inv);
    }
}

// ---------------- launch ----------------------------------------------------
extern "C" void kernel_launch(void* const* d_in, const int* in_sizes, int n_in,
                              void* d_out, int out_size) {
    const float* x    = (const float*)d_in[0];
    const float* temb = (const float*)d_in[1];
    const float* wr   = (const float*)d_in[2];
    const float* wi   = (const float*)d_in[3];
    const float* dw   = (const float*)d_in[4];
    const float* db   = (const float*)d_in[5];
    float* out = (float*)d_out;

    const int fft_smem  = SBUF_ELEMS * sizeof(float2);            // 65792
    const int eins_smem = (8192 + 2 * WBUF) * sizeof(float);      // 66048
    cudaFuncSetAttribute(k_fwd,  cudaFuncAttributeMaxDynamicSharedMemorySize, fft_smem);
    cudaFuncSetAttribute(k_inv,  cudaFuncAttributeMaxDynamicSharedMemorySize, fft_smem);
    cudaFuncSetAttribute(k_eins, cudaFuncAttributeMaxDynamicSharedMemorySize, eins_smem);

    k_tw<<<32, 256>>>();
    k_temb<<<B_, 256>>>(temb, dw, db);
    k_fwd<<<B_ * CI, 256, fft_smem>>>(x);
    k_eins<<<MODES / 4, 256, eins_smem>>>(wr, wi);
    k_inv<<<B_ * CO, 256, fft_smem>>>(out);
}

// round 4
// speedup vs baseline: 1.2523x; 1.2523x over previous
#include <cuda_runtime.h>
#include <math.h>

#define B_    16
#define CI    64
#define CO    64
#define NN    16384
#define MODES 2048
#define TEMBD 512
#define HN    8192   // NN/2, complex FFT length

// ---------------- scratch (device globals; no allocation allowed) ----------
__device__ float2 g_TW[HN];                 // exp(-2*pi*i*j/16384), j in [0,8192)
__device__ float  g_t[B_ * CI];             // temb projection
__device__ float2 g_xm[B_ * CI * MODES];    // 16 MB  x_ft[:, :, :modes] + t
__device__ float2 g_om[B_ * CO * MODES];    // 16 MB  einsum output

__device__ __forceinline__ float2 cmul(float2 a, float2 b) {
    return make_float2(a.x * b.x - a.y * b.y, a.x * b.y + a.y * b.x);
}
__device__ __forceinline__ float2 cadd(float2 a, float2 b) {
    return make_float2(a.x + b.x, a.y + b.y);
}
__device__ __forceinline__ float2 csub(float2 a, float2 b) {
    return make_float2(a.x - b.x, a.y - b.y);
}

__host__ __device__ constexpr int brev5c(int i) {
    return ((i & 1) << 4) | ((i & 2) << 2) | (i & 4) | ((i & 8) >> 2) | ((i & 16) >> 4);
}
__host__ __device__ constexpr int brev3c(int i) {
    return ((i & 1) << 2) | (i & 2) | ((i & 4) >> 2);
}

// padded smem index: +1 float2 per 256 (kills stride-256 bank conflicts)
#define PADI(i) ((i) + ((i) >> 8))
#define SBUF_ELEMS (HN + 32)          // 8224 float2 = 65792 B

// ---------------- cp.async helpers ------------------------------------------
__device__ __forceinline__ unsigned smem_addr_u32(const void* p) {
    return (unsigned)__cvta_generic_to_shared(p);
}
#define CP16(dst_u32, src_ptr) \
    asm volatile("cp.async.cg.shared.global [%0], [%1], 16;\n" \
                 :: "r"(dst_u32), "l"(src_ptr))
#define CPCOMMIT() asm volatile("cp.async.commit_group;\n" ::: "memory")
#define CPWAIT(n)  asm volatile("cp.async.wait_group %0;\n" :: "n"(n) : "memory")

// ---------------- twiddle table ---------------------------------------------
__global__ void k_tw() {
    int j = blockIdx.x * blockDim.x + threadIdx.x;
    if (j < HN) {
        float s, c;
        sincospif(-(float)j / (float)HN, &s, &c);   // -2*pi*j/16384
        g_TW[j] = make_float2(c, s);
    }
}

// ---------------- temb projection -------------------------------------------
__global__ void k_temb(const float* __restrict__ temb,
                       const float* __restrict__ dw,
                       const float* __restrict__ db) {
    __shared__ float red[256];
    int b   = blockIdx.x;
    int tid = threadIdx.x;
    int c   = tid & 63;
    int sl  = tid >> 6;
    const float* te = temb + b * TEMBD;
    const float* w  = dw + c * TEMBD;
    float p = 0.f;
    int k0 = sl * 128;
    #pragma unroll 4
    for (int k = k0; k < k0 + 128; k++) {
        float v = te[k];
        p += (v / (1.0f + expf(-v))) * w[k];
    }
    red[tid] = p;
    __syncthreads();
    if (sl == 0)
        g_t[b * CI + c] = red[c] + red[c + 64] + red[c + 128] + red[c + 192] + db[c];
}

// ---------------- register DIF FFT (natural in, bit-reversed out) -----------
template <int SIZE, int LOG>
__device__ __forceinline__ void fft_dif(float2* r, const float2* stw) {
    #pragma unroll
    for (int st = 0; st < LOG; st++) {
        const int span = SIZE >> (1 + st);
        #pragma unroll
        for (int g = 0; g < SIZE; g += 2 * span) {
            #pragma unroll
            for (int j = 0; j < span; j++) {
                float2 a = r[g + j];
                float2 b = r[g + j + span];
                r[g + j] = cadd(a, b);
                r[g + j + span] = cmul(csub(a, b), stw[j * (16 / span)]);
            }
        }
    }
}

// ---------------- four-step FFT-8192: 32(reg) x [32(reg) x 8(reg)] ----------
// Input : r[n1] = x[n1*256 + tid]  (caller preloads)
// Output: s[PADI(k)] = X[k] (forward) / sum e^{+2pi i} (inverse, unnormalized)
// PRUNE: only store final bins k<2048 or k>=6144 (rfft epilogue needs only those)
template <bool INV, bool PRUNE>
__device__ __forceinline__ void fft8192_4step(float2* s, const float2* stw,
                                              int tid, float2* r) {
    __syncthreads();   // protects s from previous use; stw ready

    // level 1: FFT-32 over n1 (stride 256), twiddle W_8192^{tid*k1}
    fft_dif<32, 5>(r, stw);
    {
        float2 w1 = g_TW[2 * tid];               // W_8192^tid
        if (INV) w1.y = -w1.y;
        float2 w12 = cmul(w1, w1);
        float2 w14 = cmul(w12, w12);
        float2 wc[4];
        wc[0] = make_float2(1.f, 0.f);
        wc[1] = w1;
        wc[2] = w12;
        wc[3] = cmul(w12, w1);
        #pragma unroll
        for (int g4 = 0; g4 < 8; g4++) {
            #pragma unroll
            for (int c = 0; c < 4; c++) {
                int k1 = g4 * 4 + c;
                s[k1 * 257 + tid] = cmul(r[brev5c(k1)], wc[c]);
            }
            if (g4 < 7) {
                #pragma unroll
                for (int c = 0; c < 4; c++) wc[c] = cmul(wc[c], w14);
            }
        }
    }
    __syncthreads();

    // level 2a: FFT-32 over n1' (stride 8 within each row), twiddle W_256^{n2'*k1'}
    const int k1 = tid & 31;
    const int n2p = tid >> 5;
    #pragma unroll
    for (int n1 = 0; n1 < 32; n1++)
        r[n1] = s[k1 * 257 + n1 * 8 + n2p];
    __syncthreads();
    fft_dif<32, 5>(r, stw);
    {
        float2 w2 = g_TW[64 * n2p];              // W_256^{n2'}
        if (INV) w2.y = -w2.y;
        float2 w22 = cmul(w2, w2);
        float2 w24 = cmul(w22, w22);
        float2 wc[4];
        wc[0] = make_float2(1.f, 0.f);
        wc[1] = w2;
        wc[2] = w22;
        wc[3] = cmul(w22, w2);
        #pragma unroll
        for (int g4 = 0; g4 < 8; g4++) {
            #pragma unroll
            for (int c = 0; c < 4; c++) {
                int k1p = g4 * 4 + c;
                s[k1 * 257 + k1p * 8 + n2p] = cmul(r[brev5c(k1p)], wc[c]);
            }
            if (g4 < 7) {
                #pragma unroll
                for (int c = 0; c < 4; c++) wc[c] = cmul(wc[c], w24);
            }
        }
    }
    __syncthreads();

    // level 2b: FFT-8 over n2' ; final index k = k1 + 32*k1' + 1024*k2'
    #pragma unroll
    for (int rr = 0; rr < 4; rr++) {
        const int k1b = (tid >> 5) + 8 * rr;
        #pragma unroll
        for (int j = 0; j < 8; j++)
            r[rr * 8 + j] = s[(tid & 31) * 257 + k1b * 8 + j];
    }
    __syncthreads();
    #pragma unroll
    for (int rr = 0; rr < 4; rr++)
        fft_dif<8, 3>(r + rr * 8, stw);
    #pragma unroll
    for (int rr = 0; rr < 4; rr++) {
        const int base = (tid & 31) + 32 * ((tid >> 5) + 8 * rr);
        #pragma unroll
        for (int j = 0; j < 8; j++) {
            const int bv = brev3c(j);
            if (PRUNE && bv >= 2 && bv <= 5) continue;   // bins 2048..6143 unused
            const int k = base + 1024 * bv;
            s[PADI(k)] = r[rr * 8 + j];
        }
    }
    __syncthreads();
}

// ---------------- forward: rfft (first 2048 bins) + temb bias ---------------
__global__ void __launch_bounds__(256, 2) k_fwd(const float* __restrict__ x) {
    extern __shared__ unsigned char smem_u8[];
    float2* s = (float2*)smem_u8;
    __shared__ float2 stw[16];
    int row = blockIdx.x;
    int tid = threadIdx.x;

    if (tid < 16) stw[tid] = g_TW[tid * 512];   // W_32^j

    const float2* xr = (const float2*)(x + (size_t)row * NN);
    float2 r[32];
    #pragma unroll
    for (int n1 = 0; n1 < 32; n1++) r[n1] = xr[n1 * 256 + tid];

    fft8192_4step<false, true>(s, stw, tid, r);

    float tb = g_t[row];
    float2* outp = g_xm + (size_t)row * MODES;
    #pragma unroll
    for (int k = tid; k < MODES; k += 256) {
        float2 Zk = s[PADI(k)];
        float2 Zm = s[PADI((HN - k) & (HN - 1))];
        float2 E = make_float2(0.5f * (Zk.x + Zm.x), 0.5f * (Zk.y - Zm.y));
        float2 O = make_float2(0.5f * (Zk.y + Zm.y), 0.5f * (Zm.x - Zk.x));
        float2 WO = cmul(g_TW[k], O);
        outp[k] = make_float2(E.x + WO.x + tb, E.y + WO.y);
    }
}

// ---------------- einsum: out[b,o,m] = sum_i xm[b,i,m] * (wr+iwi)[i,o,m] ----
// 512 CTAs x 4 modes, 256 threads, tile 4b x 4o x 1m.
// W staged via cp.async double buffering: 4 chunks of 16 i's, 2 stages.
// SMEM: xs 4096 float2 (32KB) + wst 2 x 8192 floats (64KB) = 96KB.
// Stage layout: real at [f*4 + mm], imag at [4096 + f*4 + mm],
//   f(ii,o) = ii*64 + (o&3)*16 + (o>>2)  -> conflict-free reads.
#define EINS_SMEM ((8192 + 16384) * 4)

__device__ __forceinline__ void eins_cp_w(const float* __restrict__ wr,
                                          const float* __restrict__ wi,
                                          unsigned wbase_u32, int stage,
                                          int ci0, int m0, int tid) {
    unsigned sb = wbase_u32 + stage * (8192 * 4);
    #pragma unroll
    for (int k = 0; k < 4; k++) {
        int idx = tid + 256 * k;     // 0..1023
        int ii  = idx >> 6;
        int o   = idx & 63;
        size_t gof = ((size_t)(ci0 + ii) * CO + o) * MODES + m0;
        int f = ii * 64 + (o & 3) * 16 + (o >> 2);
        CP16(sb + f * 16, wr + gof);
        CP16(sb + 16384 + f * 16, wi + gof);
    }
}

__global__ void __launch_bounds__(256, 2) k_eins(const float* __restrict__ wr,
                                                 const float* __restrict__ wi) {
    extern __shared__ float smf[];
    float2* xs  = (float2*)smf;            // [i][b][mm] : 64*16*4 float2 = 32KB
    float*  wst = smf + 8192;              // 2 stages x 8192 floats

    int tid = threadIdx.x;
    int m0  = blockIdx.x * 4;
    int mg  = tid & 3;
    int ogf = (tid >> 2) & 15;
    int bg  = tid >> 6;
    int b0  = bg * 4, o0 = ogf * 4;

    unsigned xs_u32 = smem_addr_u32(xs);
    unsigned w_u32  = smem_addr_u32(wst);

    // stage xs (32KB) via cp.async: 8 x 16B per thread
    #pragma unroll
    for (int k = 0; k < 8; k++) {
        int bl   = tid + 256 * k;          // 0..2047 (16B blocks)
        int p    = bl >> 1;                // (i,b) pair
        int half = bl & 1;
        int i = p >> 4, b = p & 15;
        const float2* src = g_xm + ((size_t)(b * CI + i)) * MODES + m0 + half * 2;
        CP16(xs_u32 + (unsigned)(i * 64 + b * 4 + half * 2) * 8, src);
    }
    // stage w chunk 0 + commit as group 0 (with xs)
    eins_cp_w(wr, wi, w_u32, 0, 0, m0, tid);
    CPCOMMIT();
    // stage w chunk 1 + commit as group 1
    eins_cp_w(wr, wi, w_u32, 1, 16, m0, tid);
    CPCOMMIT();

    float2 acc[4][4];
    #pragma unroll
    for (int a = 0; a < 4; a++)
        #pragma unroll
        for (int o = 0; o < 4; o++) acc[a][o] = make_float2(0.f, 0.f);

    CPWAIT(1);          // xs + chunk 0 landed
    __syncthreads();

    #pragma unroll 1
    for (int ib = 0; ib < 4; ib++) {
        const float* ws = wst + (ib & 1) * 8192;

        #pragma unroll
        for (int ii = 0; ii < 16; ii++) {
            int i = ib * 16 + ii;
            float2 xv[4];
            #pragma unroll
            for (int bb = 0; bb < 4; bb++)
                xv[bb] = xs[i * 64 + (b0 + bb) * 4 + mg];
            #pragma unroll
            for (int oo = 0; oo < 4; oo++) {
                int fo = ii * 64 + oo * 16 + ogf;
                float wrv = ws[fo * 4 + mg];
                float wiv = ws[4096 + fo * 4 + mg];
                #pragma unroll
                for (int bb = 0; bb < 4; bb++) {
                    acc[bb][oo].x += xv[bb].x * wrv - xv[bb].y * wiv;
                    acc[bb][oo].y += xv[bb].x * wiv + xv[bb].y * wrv;
                }
            }
        }

        if (ib < 3) {
            __syncthreads();               // all readers done with buf (ib&1)
            if (ib < 2) {
                eins_cp_w(wr, wi, w_u32, ib & 1, (ib + 2) * 16, m0, tid);
                CPCOMMIT();
                CPWAIT(1);                 // chunk ib+1 landed, ib+2 in flight
            } else {
                CPWAIT(0);                 // chunk 3 landed
            }
            __syncthreads();
        }
    }

    #pragma unroll
    for (int bb = 0; bb < 4; bb++)
        #pragma unroll
        for (int oo = 0; oo < 4; oo++)
            g_om[((size_t)(b0 + bb) * CO + (o0 + oo)) * MODES + m0 + mg] = acc[bb][oo];
}

// ---------------- inverse: zero-padded irfft(n=16384) of 2048 modes ---------
__global__ void __launch_bounds__(256, 2) k_inv(float* __restrict__ out) {
    extern __shared__ unsigned char smem_u8[];
    float2* s = (float2*)smem_u8;
    __shared__ float2 stw[16];
    int row = blockIdx.x;
    int tid = threadIdx.x;

    if (tid < 16) {
        float2 w = g_TW[tid * 512];
        stw[tid] = make_float2(w.x, -w.y);   // conj for inverse
    }

    const float2* Y = g_om + (size_t)row * MODES;
    // Build even/odd-packed spectrum C[k] = A[k] + i*B[k]
    for (int k = tid; k < HN; k += 256) {
        float2 Yl = make_float2(0.f, 0.f);
        float2 Yh = make_float2(0.f, 0.f);
        if (k < MODES) {
            Yl = Y[k];
            if (k == 0) Yl.y = 0.f;          // c2r ignores imag(DC)
        }
        if (k > HN - MODES) {                // k in [6145, 8191]
            float2 ym = Y[HN - k];
            Yh = make_float2(ym.x, -ym.y);
        }
        float2 A  = make_float2(Yl.x + Yh.x, Yl.y + Yh.y);
        float2 Bc = make_float2(Yl.x - Yh.x, Yl.y - Yh.y);
        float2 w  = g_TW[k];
        w.y = -w.y;                          // e^{+2pi i k/16384}
        float2 Bv = cmul(Bc, w);
        s[PADI(k)] = make_float2(A.x - Bv.y, A.y + Bv.x);
    }
    __syncthreads();

    float2 r[32];
    #pragma unroll
    for (int n1 = 0; n1 < 32; n1++)
        r[n1] = s[n1 * 257 + tid];           // PADI(n1*256+tid)

    fft8192_4step<true, false>(s, stw, tid, r);

    const float inv = 1.0f / (float)NN;
    float2* outp = (float2*)(out + (size_t)row * NN);
    #pragma unroll
    for (int m = tid; m < HN; m += 256) {
        float2 g = s[PADI(m)];
        outp[m] = make_float2(g.x * inv, g.y * inv);
    }
}

// ---------------- launch ----------------------------------------------------
extern "C" void kernel_launch(void* const* d_in, const int* in_sizes, int n_in,
                              void* d_out, int out_size) {
    const float* x    = (const float*)d_in[0];
    const float* temb = (const float*)d_in[1];
    const float* wr   = (const float*)d_in[2];
    const float* wi   = (const float*)d_in[3];
    const float* dw   = (const float*)d_in[4];
    const float* db   = (const float*)d_in[5];
    float* out = (float*)d_out;

    const int fft_smem = SBUF_ELEMS * sizeof(float2);   // 65792
    cudaFuncSetAttribute(k_fwd,  cudaFuncAttributeMaxDynamicSharedMemorySize, fft_smem);
    cudaFuncSetAttribute(k_inv,  cudaFuncAttributeMaxDynamicSharedMemorySize, fft_smem);
    cudaFuncSetAttribute(k_eins, cudaFuncAttributeMaxDynamicSharedMemorySize, EINS_SMEM);

    k_tw<<<32, 256>>>();
    k_temb<<<B_, 256>>>(temb, dw, db);
    k_fwd<<<B_ * CI, 256, fft_smem>>>(x);
    k_eins<<<MODES / 4, 256, EINS_SMEM>>>(wr, wi);
    k_inv<<<B_ * CO, 256, fft_smem>>>(out);
}